// round 1
// baseline (speedup 1.0000x reference)
#include <cuda_runtime.h>
#include <cuda_bf16.h>
#include <math.h>
#include <stdint.h>

#define BB 2
#define CC 64
#define HH 64
#define WW 96
#define C4C 256
#define HWp (HH*WW)          // 6144
#define NPIX (BB*HH*WW)      // 12288
#define NTOT (BB*CC*HH*WW)   // 786432
#define WSZ 8
#define PP 4

// ---------------- scratch (static device allocations) ----------------
__device__ float g_bn [2*BB*C4C*HWp];   // BN output, both sides
__device__ float g_y1 [2*BB*C4C*HWp];   // conv1 + leakyrelu
__device__ float g_res[2*BB*C4C*HWp];   // resblock output
__device__ float g_Q  [NTOT];           // NHWC  [b][h][w][c]
__device__ float g_K  [NTOT];
__device__ float g_xl [NTOT];           // x_left NHWC
__device__ float g_xr [NTOT];
__device__ float g_oL [NTOT];           // out_left NHWC (pre-transpose)
__device__ float g_oR [NTOT];

// ---------------- BN (eval) ----------------
__global__ void bn_kernel(const float* __restrict__ cl, const float* __restrict__ cr,
                          const float* __restrict__ g, const float* __restrict__ bt,
                          const float* __restrict__ m, const float* __restrict__ v) {
    int i = blockIdx.x * blockDim.x + threadIdx.x;
    if (i >= BB*C4C*HWp) return;
    int ch = (i / HWp) % C4C;
    float sc = g[ch] * rsqrtf(v[ch] + 1e-5f);
    float sh = bt[ch] - m[ch] * sc;
    g_bn[i]                 = fmaf(cl[i], sc, sh);
    g_bn[i + BB*C4C*HWp]    = fmaf(cr[i], sc, sh);
}

// ---------------- NCHW -> NHWC transpose of x_left/x_right ----------------
__global__ void transpose_in_kernel(const float* __restrict__ in, int which) {
    __shared__ float tile[32][33];
    float* out = which ? g_xr : g_xl;
    int b = blockIdx.z;
    const float* inb = in + (size_t)b * CC * HWp;
    float* outb      = out + (size_t)b * HWp * CC;
    int p0 = blockIdx.x * 32;   // pixel tiles (6144/32)
    int c0 = blockIdx.y * 32;   // channel tiles (64/32)
    int tx = threadIdx.x, ty = threadIdx.y;
    #pragma unroll
    for (int i = 0; i < 32; i += 8)
        tile[ty + i][tx] = inb[(size_t)(c0 + ty + i) * HWp + p0 + tx];
    __syncthreads();
    #pragma unroll
    for (int i = 0; i < 32; i += 8)
        outb[(size_t)(p0 + ty + i) * CC + c0 + tx] = tile[tx][ty + i];
}

// ---------------- NHWC -> NCHW output transpose ----------------
__global__ void transpose_out_kernel(float* __restrict__ outbase, int which) {
    __shared__ float tile[32][33];
    const float* in = which ? g_oR : g_oL;
    float* out = outbase + (size_t)which * NTOT;
    int b = blockIdx.z;
    const float* inb = in + (size_t)b * HWp * CC;
    float* outb      = out + (size_t)b * CC * HWp;
    int c0 = blockIdx.x * 32;   // channel tiles (2)
    int p0 = blockIdx.y * 32;   // pixel tiles (192)
    int tx = threadIdx.x, ty = threadIdx.y;
    #pragma unroll
    for (int i = 0; i < 32; i += 8)
        tile[ty + i][tx] = inb[(size_t)(p0 + ty + i) * CC + c0 + tx];
    __syncthreads();
    #pragma unroll
    for (int i = 0; i < 32; i += 8)
        outb[(size_t)(c0 + ty + i) * HWp + p0 + tx] = tile[tx][ty + i];
}

// ---------------- grouped 3x3 conv (groups=4) ----------------
// STAGE 0: in=g_bn, out=g_y1, LeakyReLU(0.1)
// STAGE 1: in=g_y1, out=g_res, residual add g_bn
template<int STAGE>
__global__ __launch_bounds__(256)
void conv3x3_kernel(const float* __restrict__ wgt, const float* __restrict__ bias) {
    __shared__ float in_s[8][34][34];
    __shared__ float w_s[16][8][9];

    const float* in = (STAGE == 0) ? g_bn : g_y1;
    float* out      = (STAGE == 0) ? g_y1 : g_res;

    int z = blockIdx.z;
    int oc4  = z & 3;          // 16-channel output chunk within group
    int g    = (z >> 2) & 3;   // group
    int b    = (z >> 4) & 1;   // batch
    int side = z >> 5;         // 0=left 1=right
    int h0 = blockIdx.y * 32, w0 = blockIdx.x * 32;

    const float* inb = in + ((size_t)(side*BB + b) * C4C + g*64) * HWp;
    int ocg = g*64 + oc4*16;   // global base output channel

    float acc[4][16];
    #pragma unroll
    for (int p = 0; p < 4; p++)
        #pragma unroll
        for (int o = 0; o < 16; o++) acc[p][o] = 0.f;

    int tid = threadIdx.x;
    int tx = tid & 31, ty = tid >> 5;

    for (int icb = 0; icb < 64; icb += 8) {
        __syncthreads();
        // input tile 8 x 34 x 34 (halo=1)
        for (int idx = tid; idx < 8*34*34; idx += 256) {
            int ic  = idx / (34*34);
            int rem = idx % (34*34);
            int r = rem / 34, cc2 = rem % 34;
            int gy = h0 + r - 1, gx = w0 + cc2 - 1;
            float val = 0.f;
            if (gy >= 0 && gy < HH && gx >= 0 && gx < WW)
                val = inb[(size_t)(icb + ic) * HWp + gy * WW + gx];
            in_s[ic][r][cc2] = val;
        }
        // weights 16 oc x 8 ic x 9
        for (int idx = tid; idx < 16*8*9; idx += 256) {
            int oc = idx / 72;
            int rem = idx % 72;
            int ic = rem / 9, kk = rem % 9;
            w_s[oc][ic][kk] = wgt[((size_t)(ocg + oc) * 64 + icb + ic) * 9 + kk];
        }
        __syncthreads();

        #pragma unroll 1
        for (int ic = 0; ic < 8; ic++) {
            #pragma unroll
            for (int kh = 0; kh < 3; kh++) {
                #pragma unroll
                for (int kw = 0; kw < 3; kw++) {
                    float i0 = in_s[ic][ty +  0 + kh][tx + kw];
                    float i1 = in_s[ic][ty +  8 + kh][tx + kw];
                    float i2 = in_s[ic][ty + 16 + kh][tx + kw];
                    float i3 = in_s[ic][ty + 24 + kh][tx + kw];
                    #pragma unroll
                    for (int oc = 0; oc < 16; oc++) {
                        float wv = w_s[oc][ic][kh*3 + kw];
                        acc[0][oc] = fmaf(i0, wv, acc[0][oc]);
                        acc[1][oc] = fmaf(i1, wv, acc[1][oc]);
                        acc[2][oc] = fmaf(i2, wv, acc[2][oc]);
                        acc[3][oc] = fmaf(i3, wv, acc[3][oc]);
                    }
                }
            }
        }
    }

    #pragma unroll
    for (int oc = 0; oc < 16; oc++) {
        float bv = bias[ocg + oc];
        #pragma unroll
        for (int p = 0; p < 4; p++) {
            float v2 = acc[p][oc] + bv;
            if (STAGE == 0) v2 = v2 > 0.f ? v2 : 0.1f * v2;   // LeakyReLU
            size_t oi = ((size_t)(side*BB + b) * C4C + ocg + oc) * HWp
                      + (size_t)(h0 + ty + p*8) * WW + (w0 + tx);
            if (STAGE == 1) v2 += g_bn[oi];                    // residual
            out[oi] = v2;
        }
    }
}

// ---------------- grouped 1x1 conv -> Q/K in NHWC ----------------
__global__ void conv1x1_kernel(const float* __restrict__ bq_w, const float* __restrict__ bq_b,
                               const float* __restrict__ bs_w, const float* __restrict__ bs_b) {
    int oc  = threadIdx.x;                       // 0..63
    int pix = blockIdx.x * 4 + threadIdx.y;      // 0..BB*HWp-1
    int side = blockIdx.y;
    int b = pix / HWp, p = pix % HWp;
    int g = oc >> 4;
    const float* inb = g_res + ((size_t)(side*BB + b) * C4C + g*64) * HWp + p;
    const float* wv = side ? bs_w : bq_w;
    float acc = side ? bs_b[oc] : bq_b[oc];
    #pragma unroll
    for (int ic = 0; ic < 64; ic++)
        acc = fmaf(inb[(size_t)ic * HWp], wv[oc*64 + ic], acc);
    float* o = side ? g_K : g_Q;
    o[(size_t)pix * CC + oc] = acc;
}

// ---------------- reductions ----------------
__device__ __forceinline__ float block2_max(float v, volatile float* red, int t) {
    #pragma unroll
    for (int o = 16; o; o >>= 1) v = fmaxf(v, __shfl_xor_sync(0xffffffffu, v, o));
    if ((t & 31) == 0) red[t >> 5] = v;
    __syncthreads();
    float r = fmaxf(red[0], red[1]);
    __syncthreads();
    return r;
}
__device__ __forceinline__ float block2_sum(float v, volatile float* red, int t) {
    #pragma unroll
    for (int o = 16; o; o >>= 1) v += __shfl_xor_sync(0xffffffffu, v, o);
    if ((t & 31) == 0) red[t >> 5] = v;
    __syncthreads();
    float r = red[0] + red[1];
    __syncthreads();
    return r;
}

// ---------------- attention: 1 block (64 threads) per pixel ----------------
// Mean-centering of patches is a uniform shift of scores -> dropped (softmax-invariant).
__global__ __launch_bounds__(64)
void attn_kernel(const int* __restrict__ d_left, const int* __restrict__ d_right) {
    __shared__ __align__(16) float q_s[64];
    __shared__ __align__(16) float k_s[64];
    __shared__ float s1_s[64], s2_s[64];
    __shared__ int   cd_s[64];
    __shared__ float red[2];

    int pix = blockIdx.x;                // b*HWp + h*W + w
    int b  = pix / HWp;
    int hp = pix % HWp;
    int h  = hp / WW, w = hp % WW;
    int t  = threadIdx.x;

    q_s[t] = g_Q[(size_t)pix * CC + t];
    k_s[t] = g_K[(size_t)pix * CC + t];

    int dl = d_left[pix], dr = d_right[pix];
    int c1 = max(w - dl, 0);             // r2l center (unpadded)
    int c2 = min(w + dr, WW - 1);        // l2r center
    bool rowok  = (h < HH - PP);
    bool valid1 = rowok && (c1 < WW - PP);
    bool valid2 = rowok && (c2 < WW - PP);
    __syncthreads();

    // scores: thread t = window position k = a*8 + bb
    int a = t >> 3, bb2 = t & 7;
    int y  = h + a - PP;
    int x1 = c1 + bb2 - PP;
    int x2 = c2 + bb2 - PP;
    bool in1 = valid1 && (y >= 0) && (y < HH) && (x1 >= 0) && (x1 < WW);
    bool in2 = valid2 && (y >= 0) && (y < HH) && (x2 >= 0) && (x2 < WW);

    float r1 = 0.f, r2 = 0.f;
    if (in1) {
        const float4* kr = (const float4*)(g_K + ((size_t)b*HWp + (size_t)y*WW + x1) * CC);
        const float4* qv = (const float4*)q_s;
        #pragma unroll
        for (int i = 0; i < 16; i++) {
            float4 kv = kr[i]; float4 q4 = qv[i];
            r1 += q4.x*kv.x + q4.y*kv.y + q4.z*kv.z + q4.w*kv.w;
        }
    }
    if (in2) {
        const float4* qr = (const float4*)(g_Q + ((size_t)b*HWp + (size_t)y*WW + x2) * CC);
        const float4* k4v = (const float4*)k_s;
        #pragma unroll
        for (int i = 0; i < 16; i++) {
            float4 qv2 = qr[i]; float4 k4 = k4v[i];
            r2 += k4.x*qv2.x + k4.y*qv2.y + k4.z*qv2.z + k4.w*qv2.w;
        }
    }
    cd_s[t] = in1 ? (y * WW + x1) : -1;   // value gathers use r2l coords (both!)

    // softmax over 64 positions (zeros for masked entries, matching reference)
    float m1 = block2_max(r1, red, t);
    float e1 = __expf(r1 - m1);
    float z1 = block2_sum(e1, red, t);
    float m2 = block2_max(r2, red, t);
    float e2 = __expf(r2 - m2);
    float z2 = block2_sum(e2, red, t);
    s1_s[t] = e1 / z1;
    s2_s[t] = e2 / z2;
    __syncthreads();

    // value aggregation: thread t = channel, coalesced NHWC reads
    const float* xrb = g_xr + (size_t)b * HWp * CC;
    const float* xlb = g_xl + (size_t)b * HWp * CC;
    float accL = 0.f, accR = 0.f;
    #pragma unroll 4
    for (int k = 0; k < 64; k++) {
        int cd = cd_s[k];
        if (cd >= 0) {
            accL = fmaf(s1_s[k], xrb[(size_t)cd * CC + t], accL);
            accR = fmaf(s2_s[k], xlb[(size_t)cd * CC + t], accR);
        }
    }
    float VL = (w - dl >= 0)     ? 1.f : 0.f;
    float VR = (w + dr <= WW-1)  ? 1.f : 0.f;
    size_t oi = (size_t)pix * CC + t;
    g_oL[oi] = xlb[(size_t)hp * CC + t] + VL * accL;
    g_oR[oi] = xrb[(size_t)hp * CC + t] + VR * accR;
}

// ---------------- launch ----------------
extern "C" void kernel_launch(void* const* d_in, const int* in_sizes, int n_in,
                              void* d_out, int out_size) {
    (void)n_in; (void)out_size;
    const float *xl, *xr, *cl, *cr, *bg, *bbeta, *bm, *bv;
    const float *w1, *b1, *w2, *b2, *bqw, *bqb, *bsw, *bsb;
    const int *dl, *dr;

    if (in_sizes[4] == BB*HH*WW) {
        // setup_inputs dict order
        xl  = (const float*)d_in[0];  xr  = (const float*)d_in[1];
        cl  = (const float*)d_in[2];  cr  = (const float*)d_in[3];
        dl  = (const int*)  d_in[4];  dr  = (const int*)  d_in[5];
        bg  = (const float*)d_in[6];  bbeta=(const float*)d_in[7];
        bm  = (const float*)d_in[8];  bv  = (const float*)d_in[9];
        w1  = (const float*)d_in[10]; b1  = (const float*)d_in[11];
        w2  = (const float*)d_in[12]; b2  = (const float*)d_in[13];
        bqw = (const float*)d_in[14]; bqb = (const float*)d_in[15];
        bsw = (const float*)d_in[16]; bsb = (const float*)d_in[17];
    } else {
        // reference() signature order
        xl  = (const float*)d_in[0];  xr  = (const float*)d_in[1];
        cl  = (const float*)d_in[2];  cr  = (const float*)d_in[3];
        bg  = (const float*)d_in[4];  bbeta=(const float*)d_in[5];
        bm  = (const float*)d_in[6];  bv  = (const float*)d_in[7];
        w1  = (const float*)d_in[8];  b1  = (const float*)d_in[9];
        w2  = (const float*)d_in[10]; b2  = (const float*)d_in[11];
        bqw = (const float*)d_in[12]; bqb = (const float*)d_in[13];
        bsw = (const float*)d_in[14]; bsb = (const float*)d_in[15];
        dl  = (const int*)  d_in[16]; dr  = (const int*)  d_in[17];
    }

    dim3 tb(32, 8);

    bn_kernel<<<(BB*C4C*HWp + 255)/256, 256>>>(cl, cr, bg, bbeta, bm, bv);
    transpose_in_kernel<<<dim3(HWp/32, CC/32, BB), tb>>>(xl, 0);
    transpose_in_kernel<<<dim3(HWp/32, CC/32, BB), tb>>>(xr, 1);

    conv3x3_kernel<0><<<dim3(WW/32, HH/32, 64), 256>>>(w1, b1);
    conv3x3_kernel<1><<<dim3(WW/32, HH/32, 64), 256>>>(w2, b2);

    conv1x1_kernel<<<dim3(BB*HWp/4, 2), dim3(64, 4)>>>(bqw, bqb, bsw, bsb);

    attn_kernel<<<NPIX, 64>>>(dl, dr);

    transpose_out_kernel<<<dim3(CC/32, HWp/32, BB), tb>>>((float*)d_out, 0);
    transpose_out_kernel<<<dim3(CC/32, HWp/32, BB), tb>>>((float*)d_out, 1);
}

// round 3
// speedup vs baseline: 1.4583x; 1.4583x over previous
#include <cuda_runtime.h>
#include <cuda_bf16.h>
#include <math.h>
#include <stdint.h>

#define BB 2
#define CC 64
#define HH 64
#define WW 96
#define C4C 256
#define HWp (HH*WW)          // 6144
#define NPIX (BB*HH*WW)      // 12288
#define NTOT (BB*CC*HH*WW)   // 786432
#define WSZ 8
#define PP 4

// ---------------- packed f32x2 helpers (sm_100+) ----------------
__device__ __forceinline__ uint64_t pack2(float lo, float hi) {
    uint64_t r;
    asm("mov.b64 %0, {%1, %2};" : "=l"(r) : "f"(lo), "f"(hi));
    return r;
}
__device__ __forceinline__ void unpack2(uint64_t v, float& lo, float& hi) {
    asm("mov.b64 {%0, %1}, %2;" : "=f"(lo), "=f"(hi) : "l"(v));
}
__device__ __forceinline__ void ffma2(uint64_t& d, uint64_t a, uint64_t b) {
    asm("fma.rn.f32x2 %0, %1, %2, %0;" : "+l"(d) : "l"(a), "l"(b));
}

// ---------------- scratch (static device allocations) ----------------
__device__ float g_bn [2*BB*C4C*HWp];   // BN output, both sides
__device__ float g_y1 [2*BB*C4C*HWp];   // conv1 + leakyrelu
__device__ float g_res[2*BB*C4C*HWp];   // resblock output
__device__ float g_Q  [NTOT];           // NHWC  [b][h][w][c]
__device__ float g_K  [NTOT];
__device__ float g_xl [NTOT];           // x_left NHWC
__device__ float g_xr [NTOT];
__device__ float g_oL [NTOT];           // out_left NHWC (pre-transpose)
__device__ float g_oR [NTOT];

// ---------------- BN (eval) ----------------
__global__ void bn_kernel(const float* __restrict__ cl, const float* __restrict__ cr,
                          const float* __restrict__ g, const float* __restrict__ bt,
                          const float* __restrict__ m, const float* __restrict__ v) {
    int i = blockIdx.x * blockDim.x + threadIdx.x;
    if (i >= BB*C4C*HWp) return;
    int ch = (i / HWp) % C4C;
    float sc = g[ch] * rsqrtf(v[ch] + 1e-5f);
    float sh = bt[ch] - m[ch] * sc;
    g_bn[i]                 = fmaf(cl[i], sc, sh);
    g_bn[i + BB*C4C*HWp]    = fmaf(cr[i], sc, sh);
}

// ---------------- NCHW -> NHWC transpose of x_left/x_right ----------------
__global__ void transpose_in_kernel(const float* __restrict__ in, int which) {
    __shared__ float tile[32][33];
    float* out = which ? g_xr : g_xl;
    int b = blockIdx.z;
    const float* inb = in + (size_t)b * CC * HWp;
    float* outb      = out + (size_t)b * HWp * CC;
    int p0 = blockIdx.x * 32;
    int c0 = blockIdx.y * 32;
    int tx = threadIdx.x, ty = threadIdx.y;
    #pragma unroll
    for (int i = 0; i < 32; i += 8)
        tile[ty + i][tx] = inb[(size_t)(c0 + ty + i) * HWp + p0 + tx];
    __syncthreads();
    #pragma unroll
    for (int i = 0; i < 32; i += 8)
        outb[(size_t)(p0 + ty + i) * CC + c0 + tx] = tile[tx][ty + i];
}

// ---------------- NHWC -> NCHW output transpose ----------------
__global__ void transpose_out_kernel(float* __restrict__ outbase, int which) {
    __shared__ float tile[32][33];
    const float* in = which ? g_oR : g_oL;
    float* out = outbase + (size_t)which * NTOT;
    int b = blockIdx.z;
    const float* inb = in + (size_t)b * HWp * CC;
    float* outb      = out + (size_t)b * CC * HWp;
    int c0 = blockIdx.x * 32;
    int p0 = blockIdx.y * 32;
    int tx = threadIdx.x, ty = threadIdx.y;
    #pragma unroll
    for (int i = 0; i < 32; i += 8)
        tile[ty + i][tx] = inb[(size_t)(p0 + ty + i) * CC + c0 + tx];
    __syncthreads();
    #pragma unroll
    for (int i = 0; i < 32; i += 8)
        outb[(size_t)(c0 + ty + i) * HWp + p0 + tx] = tile[tx][ty + i];
}

// ---------------- grouped 3x3 conv (groups=4), f32x2 packed math ----------------
// STAGE 0: in=g_bn, out=g_y1, LeakyReLU(0.1)
// STAGE 1: in=g_y1, out=g_res, residual add g_bn
template<int STAGE>
__global__ __launch_bounds__(256)
void conv3x3_kernel(const float* __restrict__ wgt, const float* __restrict__ bias) {
    __shared__ float  in_s[8][34][34];
    __shared__ float2 w_s[16][8][9];   // duplicated {w,w} for packed FMA

    const float* in = (STAGE == 0) ? g_bn : g_y1;
    float* out      = (STAGE == 0) ? g_y1 : g_res;

    int z = blockIdx.z;
    int oc4  = z & 3;
    int g    = (z >> 2) & 3;
    int b    = (z >> 4) & 1;
    int side = z >> 5;
    int h0 = blockIdx.y * 32, w0 = blockIdx.x * 32;

    const float* inb = in + ((size_t)(side*BB + b) * C4C + g*64) * HWp;
    int ocg = g*64 + oc4*16;

    uint64_t acc01[16], acc23[16];
    #pragma unroll
    for (int o = 0; o < 16; o++) { acc01[o] = 0ull; acc23[o] = 0ull; }

    int tid = threadIdx.x;
    int tx = tid & 31, ty = tid >> 5;

    for (int icb = 0; icb < 64; icb += 8) {
        __syncthreads();
        // input tile 8 x 34 x 34 (halo=1)
        for (int idx = tid; idx < 8*34*34; idx += 256) {
            int ic  = idx / (34*34);
            int rem = idx % (34*34);
            int r = rem / 34, cc2 = rem % 34;
            int gy = h0 + r - 1, gx = w0 + cc2 - 1;
            float val = 0.f;
            if (gy >= 0 && gy < HH && gx >= 0 && gx < WW)
                val = inb[(size_t)(icb + ic) * HWp + gy * WW + gx];
            in_s[ic][r][cc2] = val;
        }
        // weights 16 oc x 8 ic x 9, duplicated into float2
        for (int idx = tid; idx < 16*8*9; idx += 256) {
            int oc = idx / 72;
            int rem = idx % 72;
            int ic = rem / 9, kk = rem % 9;
            float wv = wgt[((size_t)(ocg + oc) * 64 + icb + ic) * 9 + kk];
            w_s[oc][ic][kk] = make_float2(wv, wv);
        }
        __syncthreads();

        #pragma unroll 1
        for (int ic = 0; ic < 8; ic++) {
            #pragma unroll
            for (int kh = 0; kh < 3; kh++) {
                #pragma unroll
                for (int kw = 0; kw < 3; kw++) {
                    float i0 = in_s[ic][ty +  0 + kh][tx + kw];
                    float i1 = in_s[ic][ty +  8 + kh][tx + kw];
                    float i2 = in_s[ic][ty + 16 + kh][tx + kw];
                    float i3 = in_s[ic][ty + 24 + kh][tx + kw];
                    uint64_t a01 = pack2(i0, i1);
                    uint64_t a23 = pack2(i2, i3);
                    const uint64_t* wp = (const uint64_t*)&w_s[0][ic][kh*3 + kw];
                    #pragma unroll
                    for (int oc = 0; oc < 16; oc++) {
                        uint64_t wv = wp[(size_t)oc * (8*9)];
                        ffma2(acc01[oc], a01, wv);
                        ffma2(acc23[oc], a23, wv);
                    }
                }
            }
        }
    }

    #pragma unroll
    for (int oc = 0; oc < 16; oc++) {
        float bv = bias[ocg + oc];
        float v0, v1, v2, v3;
        unpack2(acc01[oc], v0, v1);
        unpack2(acc23[oc], v2, v3);
        float vv[4] = {v0, v1, v2, v3};
        #pragma unroll
        for (int p = 0; p < 4; p++) {
            float val = vv[p] + bv;
            if (STAGE == 0) val = val > 0.f ? val : 0.1f * val;   // LeakyReLU
            size_t oi = ((size_t)(side*BB + b) * C4C + ocg + oc) * HWp
                      + (size_t)(h0 + ty + p*8) * WW + (w0 + tx);
            if (STAGE == 1) val += g_bn[oi];                      // residual
            out[oi] = val;
        }
    }
}

// ---------------- grouped 1x1 conv -> Q/K in NHWC (smem-tiled, per-group) ----------------
// Block: 256 threads = 16 oc x 16 pixel-quads (4 px each). Grid: (pixel tiles, group, side)
__global__ __launch_bounds__(256)
void conv1x1_kernel(const float* __restrict__ bq_w, const float* __restrict__ bq_b,
                    const float* __restrict__ bs_w, const float* __restrict__ bs_b) {
    __shared__ float in_s[64][64];      // 16 KB: 64 group-channels x 64 pixels
    __shared__ float w_sh[16][64];      // 4 KB:  16 oc x 64 ic

    int side = blockIdx.z;
    int g    = blockIdx.y;
    int p0   = blockIdx.x * 64;         // tile start within [0, BB*HWp)
    int b    = p0 / HWp;
    int tid  = threadIdx.x;

    const float* wsrc = side ? bs_w : bq_w;
    const float* bsrc = side ? bs_b : bq_b;

    // stage weights: oc in [g*16, g*16+16), ic local 0..63
    for (int i = tid; i < 16*64; i += 256) {
        int oc = i >> 6, ic = i & 63;
        w_sh[oc][ic] = wsrc[(g*16 + oc)*64 + ic];
    }

    // stage input tile: 64 group channels x 64 consecutive pixels (coalesced)
    const float* resb = g_res + ((size_t)(side*BB + b) * C4C + g*64) * HWp + (p0 - b*HWp);
    for (int i = tid; i < 64*64; i += 256) {
        int ch = i >> 6, px = i & 63;
        in_s[ch][px] = resb[(size_t)ch * HWp + px];
    }
    __syncthreads();

    int oc = tid & 15;          // local output channel (0..15)
    int pq = tid >> 4;          // pixel quad (0..15), 4 px each

    uint64_t acc[2] = {0ull, 0ull};
    #pragma unroll 8
    for (int ic = 0; ic < 64; ic++) {
        float wv = w_sh[oc][ic];
        uint64_t ww = pack2(wv, wv);
        const uint64_t* irow = (const uint64_t*)&in_s[ic][pq*4];
        ffma2(acc[0], irow[0], ww);
        ffma2(acc[1], irow[1], ww);
    }

    float bv = bsrc[g*16 + oc];
    float* o = side ? g_K : g_Q;
    int ocg = g*16 + oc;
    #pragma unroll
    for (int j = 0; j < 2; j++) {
        float lo, hi;
        unpack2(acc[j], lo, hi);
        int px = pq*4 + 2*j;
        o[(size_t)(p0 + px    ) * CC + ocg] = lo + bv;
        o[(size_t)(p0 + px + 1) * CC + ocg] = hi + bv;
    }
}

// ---------------- reductions ----------------
__device__ __forceinline__ float block2_max(float v, volatile float* red, int t) {
    #pragma unroll
    for (int o = 16; o; o >>= 1) v = fmaxf(v, __shfl_xor_sync(0xffffffffu, v, o));
    if ((t & 31) == 0) red[t >> 5] = v;
    __syncthreads();
    float r = fmaxf(red[0], red[1]);
    __syncthreads();
    return r;
}
__device__ __forceinline__ float block2_sum(float v, volatile float* red, int t) {
    #pragma unroll
    for (int o = 16; o; o >>= 1) v += __shfl_xor_sync(0xffffffffu, v, o);
    if ((t & 31) == 0) red[t >> 5] = v;
    __syncthreads();
    float r = red[0] + red[1];
    __syncthreads();
    return r;
}

// ---------------- attention: 1 block (64 threads) per pixel ----------------
__global__ __launch_bounds__(64)
void attn_kernel(const int* __restrict__ d_left, const int* __restrict__ d_right) {
    __shared__ __align__(16) float q_s[64];
    __shared__ __align__(16) float k_s[64];
    __shared__ float s1_s[64], s2_s[64];
    __shared__ int   cd_s[64];
    __shared__ float red[2];

    int pix = blockIdx.x;
    int b  = pix / HWp;
    int hp = pix % HWp;
    int h  = hp / WW, w = hp % WW;
    int t  = threadIdx.x;

    q_s[t] = g_Q[(size_t)pix * CC + t];
    k_s[t] = g_K[(size_t)pix * CC + t];

    int dl = d_left[pix], dr = d_right[pix];
    int c1 = max(w - dl, 0);
    int c2 = min(w + dr, WW - 1);
    bool rowok  = (h < HH - PP);
    bool valid1 = rowok && (c1 < WW - PP);
    bool valid2 = rowok && (c2 < WW - PP);
    __syncthreads();

    int a = t >> 3, bb2 = t & 7;
    int y  = h + a - PP;
    int x1 = c1 + bb2 - PP;
    int x2 = c2 + bb2 - PP;
    bool in1 = valid1 && (y >= 0) && (y < HH) && (x1 >= 0) && (x1 < WW);
    bool in2 = valid2 && (y >= 0) && (y < HH) && (x2 >= 0) && (x2 < WW);

    float r1 = 0.f, r2 = 0.f;
    if (in1) {
        const float4* kr = (const float4*)(g_K + ((size_t)b*HWp + (size_t)y*WW + x1) * CC);
        const float4* qv = (const float4*)q_s;
        #pragma unroll
        for (int i = 0; i < 16; i++) {
            float4 kv = kr[i]; float4 q4 = qv[i];
            r1 += q4.x*kv.x + q4.y*kv.y + q4.z*kv.z + q4.w*kv.w;
        }
    }
    if (in2) {
        const float4* qr = (const float4*)(g_Q + ((size_t)b*HWp + (size_t)y*WW + x2) * CC);
        const float4* k4v = (const float4*)k_s;
        #pragma unroll
        for (int i = 0; i < 16; i++) {
            float4 qv2 = qr[i]; float4 k4 = k4v[i];
            r2 += k4.x*qv2.x + k4.y*qv2.y + k4.z*qv2.z + k4.w*qv2.w;
        }
    }
    cd_s[t] = in1 ? (y * WW + x1) : -1;

    float m1 = block2_max(r1, red, t);
    float e1 = __expf(r1 - m1);
    float z1 = block2_sum(e1, red, t);
    float m2 = block2_max(r2, red, t);
    float e2 = __expf(r2 - m2);
    float z2 = block2_sum(e2, red, t);
    s1_s[t] = e1 / z1;
    s2_s[t] = e2 / z2;
    __syncthreads();

    const float* xrb = g_xr + (size_t)b * HWp * CC;
    const float* xlb = g_xl + (size_t)b * HWp * CC;
    float accL = 0.f, accR = 0.f;
    #pragma unroll 4
    for (int k = 0; k < 64; k++) {
        int cd = cd_s[k];
        if (cd >= 0) {
            accL = fmaf(s1_s[k], xrb[(size_t)cd * CC + t], accL);
            accR = fmaf(s2_s[k], xlb[(size_t)cd * CC + t], accR);
        }
    }
    float VL = (w - dl >= 0)     ? 1.f : 0.f;
    float VR = (w + dr <= WW-1)  ? 1.f : 0.f;
    size_t oi = (size_t)pix * CC + t;
    g_oL[oi] = xlb[(size_t)hp * CC + t] + VL * accL;
    g_oR[oi] = xrb[(size_t)hp * CC + t] + VR * accR;
}

// ---------------- launch ----------------
extern "C" void kernel_launch(void* const* d_in, const int* in_sizes, int n_in,
                              void* d_out, int out_size) {
    (void)n_in; (void)out_size;
    const float *xl, *xr, *cl, *cr, *bg, *bbeta, *bm, *bv;
    const float *w1, *b1, *w2, *b2, *bqw, *bqb, *bsw, *bsb;
    const int *dl, *dr;

    if (in_sizes[4] == BB*HH*WW) {
        xl  = (const float*)d_in[0];  xr  = (const float*)d_in[1];
        cl  = (const float*)d_in[2];  cr  = (const float*)d_in[3];
        dl  = (const int*)  d_in[4];  dr  = (const int*)  d_in[5];
        bg  = (const float*)d_in[6];  bbeta=(const float*)d_in[7];
        bm  = (const float*)d_in[8];  bv  = (const float*)d_in[9];
        w1  = (const float*)d_in[10]; b1  = (const float*)d_in[11];
        w2  = (const float*)d_in[12]; b2  = (const float*)d_in[13];
        bqw = (const float*)d_in[14]; bqb = (const float*)d_in[15];
        bsw = (const float*)d_in[16]; bsb = (const float*)d_in[17];
    } else {
        xl  = (const float*)d_in[0];  xr  = (const float*)d_in[1];
        cl  = (const float*)d_in[2];  cr  = (const float*)d_in[3];
        bg  = (const float*)d_in[4];  bbeta=(const float*)d_in[5];
        bm  = (const float*)d_in[6];  bv  = (const float*)d_in[7];
        w1  = (const float*)d_in[8];  b1  = (const float*)d_in[9];
        w2  = (const float*)d_in[10]; b2  = (const float*)d_in[11];
        bqw = (const float*)d_in[12]; bqb = (const float*)d_in[13];
        bsw = (const float*)d_in[14]; bsb = (const float*)d_in[15];
        dl  = (const int*)  d_in[16]; dr  = (const int*)  d_in[17];
    }

    dim3 tb(32, 8);

    bn_kernel<<<(BB*C4C*HWp + 255)/256, 256>>>(cl, cr, bg, bbeta, bm, bv);
    transpose_in_kernel<<<dim3(HWp/32, CC/32, BB), tb>>>(xl, 0);
    transpose_in_kernel<<<dim3(HWp/32, CC/32, BB), tb>>>(xr, 1);

    conv3x3_kernel<0><<<dim3(WW/32, HH/32, 64), 256>>>(w1, b1);
    conv3x3_kernel<1><<<dim3(WW/32, HH/32, 64), 256>>>(w2, b2);

    conv1x1_kernel<<<dim3(BB*HWp/64, 4, 2), 256>>>(bqw, bqb, bsw, bsb);

    attn_kernel<<<NPIX, 64>>>(dl, dr);

    transpose_out_kernel<<<dim3(CC/32, HWp/32, BB), tb>>>((float*)d_out, 0);
    transpose_out_kernel<<<dim3(CC/32, HWp/32, BB), tb>>>((float*)d_out, 1);
}